// round 2
// baseline (speedup 1.0000x reference)
#include <cuda_runtime.h>

// SSIM preservation loss, fully fused.
// clean, adversarial: [32, 3, 512, 512] fp32 -> scalar fp32.
//
// Structure: one plane-tile kernel (fused 5-channel separable 11-tap Gaussian
// blur + SSIM map + partial reduction), then a tiny finalize kernel.
// Horizontal pass reads {x,y} pairs from a double-buffered shared row and
// forms x^2, y^2, xy on the fly; vertical pass is a 55-register ring with
// compile-time indices (row loop modulo-scheduled by 11 and fully unrolled).

#define IMG_H 512
#define IMG_W 512
#define N_PLANES (32 * 3)
#define TW 128               // tile width  = blockDim.x (one thread per column)
#define TH 128               // tile height (output rows per block)
#define HALO 5
#define NROWS (TH + 2 * HALO)   // 138 h-rows per tile
#define GRID_X (IMG_W / TW)     // 4
#define GRID_Y (IMG_H / TH)     // 4
#define N_BLOCKS (GRID_X * GRID_Y * N_PLANES)  // 1536
#define NPIX 25165824.0         // 32*3*512*512

// Gaussian window, size 11, sigma 1.5 (normalized). Literals so ptxas emits
// FFMA-imm (rt_SMSP=1, 2x throughput of 3-reg FFMA).
#define GW0 0.00102838f
#define GW1 0.00759874f
#define GW2 0.03600077f
#define GW3 0.10936068f
#define GW4 0.21300553f
#define GW5 0.26601172f

__device__ float g_part[N_BLOCKS];

__global__ __launch_bounds__(TW, 4)
void ssim_fused_kernel(const float* __restrict__ clean,
                       const float* __restrict__ adv) {
    const float GW[11] = {GW0, GW1, GW2, GW3, GW4, GW5, GW4, GW3, GW2, GW1, GW0};

    __shared__ float2 srow[2][TW + 2 * HALO + 2];  // double-buffered row {x,y}
    __shared__ float red[TW / 32];

    const int tid   = threadIdx.x;
    const int tileX = blockIdx.x * TW;
    const int tileY = blockIdx.y * TH;
    const size_t plane = (size_t)blockIdx.z * (size_t)(IMG_H * IMG_W);
    const float* __restrict__ cp = clean + plane;
    const float* __restrict__ ap = adv + plane;

    // vertical ring: h-blur results for the last 11 h-rows (slot = r % 11)
    float rx[11], ry[11], rxx[11], ryy[11], rxy[11];
    float acc = 0.0f;

    for (int rb = 0; rb < NROWS; rb += 11) {
#pragma unroll
        for (int t = 0; t < 11; ++t) {
            const int r = rb + t;           // h-row index, 0..137; r % 11 == t
            if (r >= NROWS) break;          // uniform across block

            // ---- cooperative load of row (TW + 10 = 138 {x,y} pairs) ----
            const int gy = tileY + r - HALO;
            float2* buf = srow[r & 1];
            {
                int idx = tid;
#pragma unroll
                for (int k = 0; k < 2; ++k) {
                    if (idx < TW + 2 * HALO) {
                        const int gx = tileX - HALO + idx;
                        float cv = 0.0f, av = 0.0f;
                        if ((unsigned)gy < IMG_H && (unsigned)gx < IMG_W) {
                            const size_t off = (size_t)gy * IMG_W + gx;
                            cv = __ldg(cp + off);
                            av = __ldg(ap + off);
                        }
                        buf[idx] = make_float2(cv, av);
                    }
                    idx += TW;
                }
            }
            __syncthreads();  // W_r -> R_r; double buffer covers W_{r+1} vs R_{r-1}

            // ---- horizontal blur (5 channels, products on the fly) ----
            float hx = 0.f, hy = 0.f, hxx = 0.f, hyy = 0.f, hxy = 0.f;
#pragma unroll
            for (int j = 0; j < 11; ++j) {
                const float2 v = buf[tid + j];
                const float x = v.x, y = v.y;
                const float w = GW[j];
                hx  = fmaf(w, x,     hx);
                hy  = fmaf(w, y,     hy);
                hxx = fmaf(w, x * x, hxx);
                hyy = fmaf(w, y * y, hyy);
                hxy = fmaf(w, x * y, hxy);
            }
            rx[t] = hx; ry[t] = hy; rxx[t] = hxx; ryy[t] = hyy; rxy[t] = hxy;

            // ---- vertical blur + SSIM once ring is full ----
            if (r >= 2 * HALO) {
                // output h-row o = r-10; h-row (o+j) lives in slot (t+1+j)%11
                float m1 = 0.f, m2 = 0.f, e11 = 0.f, e22 = 0.f, e12 = 0.f;
#pragma unroll
                for (int j = 0; j < 11; ++j) {
                    const int s = (t + 1 + j) % 11;  // compile-time
                    const float w = GW[j];
                    m1  = fmaf(w, rx[s],  m1);
                    m2  = fmaf(w, ry[s],  m2);
                    e11 = fmaf(w, rxx[s], e11);
                    e22 = fmaf(w, ryy[s], e22);
                    e12 = fmaf(w, rxy[s], e12);
                }
                const float C1 = 1e-4f, C2 = 9e-4f;
                const float m1s = m1 * m1;
                const float m2s = m2 * m2;
                const float m12 = m1 * m2;
                const float s1  = e11 - m1s;
                const float s2  = e22 - m2s;
                const float s12 = e12 - m12;
                const float num = fmaf(2.0f, m12, C1) * fmaf(2.0f, s12, C2);
                const float den = (m1s + m2s + C1) * (s1 + s2 + C2);
                acc += __fdividef(num, den);
            }
        }
    }

    // ---- block reduction -> deterministic per-block partial ----
#pragma unroll
    for (int o = 16; o; o >>= 1)
        acc += __shfl_down_sync(0xffffffffu, acc, o);
    if ((tid & 31) == 0) red[tid >> 5] = acc;
    __syncthreads();
    if (tid == 0) {
        float s = 0.0f;
#pragma unroll
        for (int w = 0; w < TW / 32; ++w) s += red[w];
        const int bid = blockIdx.x + GRID_X * (blockIdx.y + GRID_Y * blockIdx.z);
        g_part[bid] = s;
    }
}

__global__ void ssim_finalize_kernel(float* __restrict__ out) {
    __shared__ double sred[8];
    const int tid = threadIdx.x;  // 256 threads
    double s = 0.0;
    for (int i = tid; i < N_BLOCKS; i += 256) s += (double)g_part[i];
#pragma unroll
    for (int o = 16; o; o >>= 1)
        s += __shfl_down_sync(0xffffffffu, s, o);
    if ((tid & 31) == 0) sred[tid >> 5] = s;
    __syncthreads();
    if (tid == 0) {
        double tot = 0.0;
#pragma unroll
        for (int w = 0; w < 8; ++w) tot += sred[w];
        out[0] = 1.0f - (float)(tot / NPIX);
    }
}

extern "C" void kernel_launch(void* const* d_in, const int* in_sizes, int n_in,
                              void* d_out, int out_size) {
    (void)in_sizes; (void)n_in; (void)out_size;
    const float* clean = (const float*)d_in[0];
    const float* adv   = (const float*)d_in[1];
    float* out = (float*)d_out;

    dim3 grid(GRID_X, GRID_Y, N_PLANES);
    ssim_fused_kernel<<<grid, TW>>>(clean, adv);
    ssim_finalize_kernel<<<1, 256>>>(out);
}

// round 3
// speedup vs baseline: 1.5737x; 1.5737x over previous
#include <cuda_runtime.h>

// SSIM preservation loss, fully fused, warp-autonomous strips.
// clean, adversarial: [32, 3, 512, 512] fp32 -> scalar fp32.
//
// Each WARP owns a 32-column strip (loads its own 42-pixel halo row into a
// private shared buffer) -> no block-level barriers in the row loop, no warp
// convoy. Global loads for row r+1 are prefetched into registers while row r
// computes (h-blur from shared, 55-reg vertical ring with compile-time ring
// indices via an unrolled 11-step modulo schedule). Final mean folded into the
// kernel via threadfence-reduction (no second launch).

#define IMG_H 512
#define IMG_W 512
#define N_PLANES (32 * 3)
#define TW 256               // tile width = 8 warps * 32 cols
#define TH 128               // output rows per block
#define HALO 5
#define NROWS (TH + 2 * HALO)   // 138 h-rows per tile
#define GRID_X (IMG_W / TW)     // 2
#define GRID_Y (IMG_H / TH)     // 4
#define N_BLOCKS (GRID_X * GRID_Y * N_PLANES)  // 768
#define NPIX 25165824.0         // 32*3*512*512
#define WBUF 44                 // 42 used, padded

// Gaussian window, size 11, sigma 1.5 (normalized) — literals => FFMA-imm.
#define GW0 0.00102838f
#define GW1 0.00759874f
#define GW2 0.03600077f
#define GW3 0.10936068f
#define GW4 0.21300553f
#define GW5 0.26601172f

__device__ float g_part[N_BLOCKS];
__device__ unsigned int g_ticket = 0;

__global__ __launch_bounds__(256)
void ssim_fused_kernel(const float* __restrict__ clean,
                       const float* __restrict__ adv,
                       float* __restrict__ out) {
    const float GW[11] = {GW0, GW1, GW2, GW3, GW4, GW5, GW4, GW3, GW2, GW1, GW0};

    __shared__ float2 sbuf[8][2][WBUF];   // per-warp double-buffered halo row
    __shared__ float red[8];
    __shared__ int s_islast;

    const int tid  = threadIdx.x;
    const int warp = tid >> 5;
    const int lane = tid & 31;
    const int colBase = blockIdx.x * TW + warp * 32;   // this warp's strip
    const int tileY   = blockIdx.y * TH;
    const size_t plane = (size_t)blockIdx.z * (size_t)(IMG_H * IMG_W);
    const float* __restrict__ cp = clean + plane;
    const float* __restrict__ ap = adv + plane;

    const int gx0 = colBase - HALO + lane;        // always in [-5, 507+...]
    const int gx1 = gx0 + 32;                     // only lanes 0..9 use it
    const bool x0ok = (unsigned)gx0 < IMG_W;
    const bool x1ok = (lane < 10) && ((unsigned)gx1 < IMG_W);

    // vertical ring: h-blur results for last 11 h-rows (slot = r % 11)
    float rx[11], ry[11], rxx[11], ryy[11], rxy[11];
    float acc = 0.0f;

    // ---- prefetch row 0 (gy = tileY - HALO) ----
    float pc0, pa0, pc1, pa1;
    {
        const int gy = tileY - HALO;
        const bool yok = (unsigned)gy < IMG_H;
        const size_t rowoff = (size_t)gy * IMG_W;
        pc0 = (yok && x0ok) ? __ldg(cp + rowoff + gx0) : 0.0f;
        pa0 = (yok && x0ok) ? __ldg(ap + rowoff + gx0) : 0.0f;
        pc1 = (yok && x1ok) ? __ldg(cp + rowoff + gx1) : 0.0f;
        pa1 = (yok && x1ok) ? __ldg(ap + rowoff + gx1) : 0.0f;
    }

    for (int rb = 0; rb < NROWS; rb += 11) {
#pragma unroll
        for (int t = 0; t < 11; ++t) {
            const int r = rb + t;           // h-row index; r % 11 == t
            if (r >= NROWS) break;          // uniform across block

            // ---- commit prefetched row r to this warp's shared buffer ----
            float2* buf = sbuf[warp][r & 1];
            buf[lane] = make_float2(pc0, pa0);
            if (lane < 10) buf[lane + 32] = make_float2(pc1, pa1);
            __syncwarp();

            // ---- issue prefetch for row r+1 (hidden behind compute) ----
            {
                const int gy = tileY + (r + 1) - HALO;
                const bool yok = (r + 1 < NROWS) && ((unsigned)gy < IMG_H);
                const size_t rowoff = (size_t)gy * IMG_W;
                pc0 = (yok && x0ok) ? __ldg(cp + rowoff + gx0) : 0.0f;
                pa0 = (yok && x0ok) ? __ldg(ap + rowoff + gx0) : 0.0f;
                pc1 = (yok && x1ok) ? __ldg(cp + rowoff + gx1) : 0.0f;
                pa1 = (yok && x1ok) ? __ldg(ap + rowoff + gx1) : 0.0f;
            }

            // ---- horizontal blur (5 channels, products on the fly) ----
            float hx = 0.f, hy = 0.f, hxx = 0.f, hyy = 0.f, hxy = 0.f;
#pragma unroll
            for (int j = 0; j < 11; ++j) {
                const float2 v = buf[lane + j];
                const float x = v.x, y = v.y;
                const float w = GW[j];
                hx  = fmaf(w, x,     hx);
                hy  = fmaf(w, y,     hy);
                hxx = fmaf(w, x * x, hxx);
                hyy = fmaf(w, y * y, hyy);
                hxy = fmaf(w, x * y, hxy);
            }
            rx[t] = hx; ry[t] = hy; rxx[t] = hxx; ryy[t] = hyy; rxy[t] = hxy;

            // ---- vertical blur + SSIM once ring is full ----
            if (r >= 2 * HALO) {
                float m1 = 0.f, m2 = 0.f, e11 = 0.f, e22 = 0.f, e12 = 0.f;
#pragma unroll
                for (int j = 0; j < 11; ++j) {
                    const int s = (t + 1 + j) % 11;  // compile-time constant
                    const float w = GW[j];
                    m1  = fmaf(w, rx[s],  m1);
                    m2  = fmaf(w, ry[s],  m2);
                    e11 = fmaf(w, rxx[s], e11);
                    e22 = fmaf(w, ryy[s], e22);
                    e12 = fmaf(w, rxy[s], e12);
                }
                const float C1 = 1e-4f, C2 = 9e-4f;
                const float m1s = m1 * m1;
                const float m2s = m2 * m2;
                const float m12 = m1 * m2;
                const float s1  = e11 - m1s;
                const float s2  = e22 - m2s;
                const float s12 = e12 - m12;
                const float num = fmaf(2.0f, m12, C1) * fmaf(2.0f, s12, C2);
                const float den = (m1s + m2s + C1) * (s1 + s2 + C2);
                acc += __fdividef(num, den);
            }
        }
    }

    // ---- block reduction -> deterministic per-block partial ----
#pragma unroll
    for (int o = 16; o; o >>= 1)
        acc += __shfl_down_sync(0xffffffffu, acc, o);
    if (lane == 0) red[warp] = acc;
    __syncthreads();

    const int bid = blockIdx.x + GRID_X * (blockIdx.y + GRID_Y * blockIdx.z);
    if (tid == 0) {
        float s = 0.0f;
#pragma unroll
        for (int w = 0; w < 8; ++w) s += red[w];
        g_part[bid] = s;
        __threadfence();                       // publish partial
        unsigned int old = atomicAdd(&g_ticket, 1u);
        s_islast = (old == N_BLOCKS - 1) ? 1 : 0;
    }
    __syncthreads();

    // ---- last block computes the global mean (threadfence-reduction) ----
    if (s_islast) {
        __shared__ double sred[8];
        volatile float* vp = g_part;
        double s = 0.0;
        for (int i = tid; i < N_BLOCKS; i += 256) s += (double)vp[i];
#pragma unroll
        for (int o = 16; o; o >>= 1)
            s += __shfl_down_sync(0xffffffffu, s, o);
        if (lane == 0) sred[warp] = s;
        __syncthreads();
        if (tid == 0) {
            double tot = 0.0;
#pragma unroll
            for (int w = 0; w < 8; ++w) tot += sred[w];
            out[0] = 1.0f - (float)(tot / NPIX);
            g_ticket = 0;                      // reset for next graph replay
        }
    }
}

extern "C" void kernel_launch(void* const* d_in, const int* in_sizes, int n_in,
                              void* d_out, int out_size) {
    (void)in_sizes; (void)n_in; (void)out_size;
    const float* clean = (const float*)d_in[0];
    const float* adv   = (const float*)d_in[1];
    float* out = (float*)d_out;

    dim3 grid(GRID_X, GRID_Y, N_PLANES);
    ssim_fused_kernel<<<grid, 256>>>(clean, adv, out);
}

// round 7
// speedup vs baseline: 1.5818x; 1.0051x over previous
#include <cuda_runtime.h>

// SSIM preservation loss, fully fused, warp-autonomous strips + f32x2 packing.
// clean, adversarial: [32, 3, 512, 512] fp32 -> scalar fp32.
//
// The 5 blur channels packed into f32x2 lanes:
//   (x,y)   -> one 64-bit packed reg, blurred with fma.rn.f32x2
//   (x2,y2) -> mul.rn.f32x2(v,v),     blurred with fma.rn.f32x2
//   (xy)    -> scalar FFMA (imm-form weights)
// cutting issue slots per h-row ~36% (R3 ncu: issue=66%, fma=46%, occ=22% --
// issue-slot limited, so time ~ instruction count).

#define IMG_H 512
#define IMG_W 512
#define N_PLANES (32 * 3)
#define TW 256               // tile width = 8 warps * 32 cols
#define TH 128               // output rows per block
#define HALO 5
#define NROWS (TH + 2 * HALO)   // 138 h-rows per tile
#define GRID_X (IMG_W / TW)     // 2
#define GRID_Y (IMG_H / TH)     // 4
#define N_BLOCKS (GRID_X * GRID_Y * N_PLANES)  // 768
#define NPIX 25165824.0         // 32*3*512*512
#define WBUF 44                 // 42 used, padded

// Gaussian window, size 11, sigma 1.5 (normalized).
#define GW0 0.00102838f
#define GW1 0.00759874f
#define GW2 0.03600077f
#define GW3 0.10936068f
#define GW4 0.21300553f
#define GW5 0.26601172f

typedef unsigned long long u64;

// weight for tap j (compile-time after full unroll)
__device__ __forceinline__ float gwj(int j) {
    switch (j) {
        case 0: case 10: return GW0;
        case 1: case 9:  return GW1;
        case 2: case 8:  return GW2;
        case 3: case 7:  return GW3;
        case 4: case 6:  return GW4;
        default:         return GW5;
    }
}

__device__ __forceinline__ u64 pack2(float lo, float hi) {
    u64 r; asm("mov.b64 %0, {%1, %2};" : "=l"(r) : "f"(lo), "f"(hi)); return r;
}
__device__ __forceinline__ void unpack2(u64 v, float& lo, float& hi) {
    asm("mov.b64 {%0, %1}, %2;" : "=f"(lo), "=f"(hi) : "l"(v));
}
__device__ __forceinline__ u64 fma2(u64 a, u64 b, u64 c) {
    u64 d; asm("fma.rn.f32x2 %0, %1, %2, %3;" : "=l"(d) : "l"(a), "l"(b), "l"(c)); return d;
}
__device__ __forceinline__ u64 mul2(u64 a, u64 b) {
    u64 d; asm("mul.rn.f32x2 %0, %1, %2;" : "=l"(d) : "l"(a), "l"(b)); return d;
}

__device__ float g_part[N_BLOCKS];
__device__ unsigned int g_ticket = 0;

__global__ __launch_bounds__(256)
void ssim_fused_kernel(const float* __restrict__ clean,
                       const float* __restrict__ adv,
                       float* __restrict__ out) {
    __shared__ u64 sbuf[8][2][WBUF];   // per-warp double-buffered halo row (x,y)
    __shared__ float red[8];
    __shared__ int s_islast;

    const int tid  = threadIdx.x;
    const int warp = tid >> 5;
    const int lane = tid & 31;
    const int colBase = blockIdx.x * TW + warp * 32;
    const int tileY   = blockIdx.y * TH;
    const size_t plane = (size_t)blockIdx.z * (size_t)(IMG_H * IMG_W);
    const float* __restrict__ cp = clean + plane;
    const float* __restrict__ ap = adv + plane;

    const int gx0 = colBase - HALO + lane;
    const int gx1 = gx0 + 32;                     // lanes 0..9 only
    const bool x0ok = (unsigned)gx0 < IMG_W;
    const bool x1ok = (lane < 10) && ((unsigned)gx1 < IMG_W);

    // vertical ring (slot = r % 11): rv=(hx,hy), rs=(hxx,hyy), rxy scalar
    u64 rv[11], rs[11];
    float rxy[11];
    float acc = 0.0f;

    // ---- prefetch row 0 (gy = tileY - HALO) ----
    float pc0, pa0, pc1, pa1;
    {
        const int gy = tileY - HALO;
        const bool yok = (unsigned)gy < IMG_H;
        const size_t rowoff = (size_t)gy * IMG_W;
        pc0 = (yok && x0ok) ? __ldg(cp + rowoff + gx0) : 0.0f;
        pa0 = (yok && x0ok) ? __ldg(ap + rowoff + gx0) : 0.0f;
        pc1 = (yok && x1ok) ? __ldg(cp + rowoff + gx1) : 0.0f;
        pa1 = (yok && x1ok) ? __ldg(ap + rowoff + gx1) : 0.0f;
    }

    for (int rb = 0; rb < NROWS; rb += 11) {
#pragma unroll
        for (int t = 0; t < 11; ++t) {
            const int r = rb + t;           // h-row index; r % 11 == t
            if (r >= NROWS) break;          // uniform across block

            // ---- commit prefetched row r to this warp's shared buffer ----
            u64* buf = sbuf[warp][r & 1];
            buf[lane] = pack2(pc0, pa0);
            if (lane < 10) buf[lane + 32] = pack2(pc1, pa1);
            __syncwarp();

            // ---- issue prefetch for row r+1 (hidden behind compute) ----
            {
                const int gy = tileY + (r + 1) - HALO;
                const bool yok = (r + 1 < NROWS) && ((unsigned)gy < IMG_H);
                const size_t rowoff = (size_t)gy * IMG_W;
                pc0 = (yok && x0ok) ? __ldg(cp + rowoff + gx0) : 0.0f;
                pa0 = (yok && x0ok) ? __ldg(ap + rowoff + gx0) : 0.0f;
                pc1 = (yok && x1ok) ? __ldg(cp + rowoff + gx1) : 0.0f;
                pa1 = (yok && x1ok) ? __ldg(ap + rowoff + gx1) : 0.0f;
            }

            // ---- horizontal blur: packed (x,y) & (x2,y2), scalar xy ----
            u64 hv = 0ull, hs = 0ull;
            float hxy = 0.0f;
#pragma unroll
            for (int j = 0; j < 11; ++j) {
                const u64 v = buf[lane + j];
                float x, y; unpack2(v, x, y);
                const u64 w2 = pack2(gwj(j), gwj(j));   // folds to constant
                hv  = fma2(w2, v, hv);
                hs  = fma2(w2, mul2(v, v), hs);
                hxy = fmaf(gwj(j), x * y, hxy);
            }
            rv[t] = hv; rs[t] = hs; rxy[t] = hxy;

            // ---- vertical blur + SSIM once ring is full ----
            if (r >= 2 * HALO) {
                u64 mv = 0ull, ev = 0ull;     // (m1,m2), (e11,e22)
                float e12 = 0.0f;
#pragma unroll
                for (int j = 0; j < 11; ++j) {
                    const int s = (t + 1 + j) % 11;   // compile-time
                    const u64 w2 = pack2(gwj(j), gwj(j));
                    mv  = fma2(w2, rv[s], mv);
                    ev  = fma2(w2, rs[s], ev);
                    e12 = fmaf(gwj(j), rxy[s], e12);
                }
                float m1, m2, e11, e22;
                unpack2(mv, m1, m2);
                unpack2(ev, e11, e22);
                const float C1 = 1e-4f, C2 = 9e-4f;
                const float m1s = m1 * m1;
                const float m2s = m2 * m2;
                const float m12 = m1 * m2;
                const float s1  = e11 - m1s;
                const float s2  = e22 - m2s;
                const float s12 = e12 - m12;
                const float num = fmaf(2.0f, m12, C1) * fmaf(2.0f, s12, C2);
                const float den = (m1s + m2s + C1) * (s1 + s2 + C2);
                acc += __fdividef(num, den);
            }
        }
    }

    // ---- block reduction -> deterministic per-block partial ----
#pragma unroll
    for (int o = 16; o; o >>= 1)
        acc += __shfl_down_sync(0xffffffffu, acc, o);
    if (lane == 0) red[warp] = acc;
    __syncthreads();

    const int bid = blockIdx.x + GRID_X * (blockIdx.y + GRID_Y * blockIdx.z);
    if (tid == 0) {
        float s = 0.0f;
#pragma unroll
        for (int w = 0; w < 8; ++w) s += red[w];
        g_part[bid] = s;
        __threadfence();
        unsigned int old = atomicAdd(&g_ticket, 1u);
        s_islast = (old == N_BLOCKS - 1) ? 1 : 0;
    }
    __syncthreads();

    // ---- last block computes the global mean ----
    if (s_islast) {
        __shared__ double sred[8];
        volatile float* vp = g_part;
        double s = 0.0;
        for (int i = tid; i < N_BLOCKS; i += 256) s += (double)vp[i];
#pragma unroll
        for (int o = 16; o; o >>= 1)
            s += __shfl_down_sync(0xffffffffu, s, o);
        if (lane == 0) sred[warp] = s;
        __syncthreads();
        if (tid == 0) {
            double tot = 0.0;
#pragma unroll
            for (int w = 0; w < 8; ++w) tot += sred[w];
            out[0] = 1.0f - (float)(tot / NPIX);
            g_ticket = 0;                      // reset for next graph replay
        }
    }
}

extern "C" void kernel_launch(void* const* d_in, const int* in_sizes, int n_in,
                              void* d_out, int out_size) {
    (void)in_sizes; (void)n_in; (void)out_size;
    const float* clean = (const float*)d_in[0];
    const float* adv   = (const float*)d_in[1];
    float* out = (float*)d_out;

    dim3 grid(GRID_X, GRID_Y, N_PLANES);
    ssim_fused_kernel<<<grid, 256>>>(clean, adv, out);
}